// round 7
// baseline (speedup 1.0000x reference)
#include <cuda_runtime.h>
#include <cuda_fp16.h>
#include <cstdint>

#define NN      50000
#define EE      800000
#define ETOT    (EE + NN)        // edges + self loops
#define IN_CH   256
#define HIDC    64
#define HEADS   2
#define C1      (HEADS * HIDC)   // 128
#define BN_EPS  1e-5f

// ---------------- scratch (static device arrays; no allocation) --------------
__device__ __half g_xl1h[NN * C1];   // fp16 edge operands (gather traffic /2)
__device__ __half g_xr1h[NN * C1];
__device__ float  g_sum1[NN * HEADS];
__device__ float  g_h1 [NN * C1];    // layer-1: accumulates sum(p * xl), fp32
__device__ __half g_xl2h[NN * HIDC];
__device__ __half g_xr2h[NN * HIDC];
__device__ float  g_sum2[NN];
__device__ float  g_h2 [NN * HIDC];  // layer-2: accumulates sum(p * xl), fp32

// ---------------- helpers ----------------------------------------------------
typedef unsigned long long u64;

__device__ __forceinline__ float lrelu(float v) { return v > 0.f ? v : 0.2f * v; }

__device__ __forceinline__ void red_add_v4(float* addr, float4 v) {
    asm volatile("red.global.add.v4.f32 [%0], {%1, %2, %3, %4};"
                 :: "l"(addr), "f"(v.x), "f"(v.y), "f"(v.z), "f"(v.w) : "memory");
}

// packed f32x2 helpers (FFMA2 — only reachable via PTX on sm_103a)
__device__ __forceinline__ u64 pack2(float lo, float hi) {
    u64 r;
    asm("mov.b64 %0, {%1, %2};" : "=l"(r) : "f"(lo), "f"(hi));
    return r;
}
__device__ __forceinline__ void ffma2(u64& acc, u64 a, u64 b) {
    asm("fma.rn.f32x2 %0, %1, %2, %0;" : "+l"(acc) : "l"(a), "l"(b));
}
__device__ __forceinline__ float2 unpack2(u64 v) {
    float lo, hi;
    asm("mov.b64 {%0, %1}, %2;" : "=f"(lo), "=f"(hi) : "l"(v));
    return make_float2(lo, hi);
}

// ---------------- dual GEMM core (k-pair packed FFMA2) -----------------------
// Tile: 64 rows x 2M cols. blockDim = (M/2)*8. Thread = (quad, rg):
// quad owns 4 adjacent cols (within one matrix), rg owns 8 rows.
// Each b64 accumulator = (sum over even k, sum over odd k); final = lo + hi.
// xs is ROW-MAJOR [64][K]: staging is coalesced & conflict-free; inner-loop
// x reads are uniform broadcast LDS.64 (address depends only on rg, k).
// Caller must have staged xs and issued __syncthreads().
template<int K, int M>
__device__ __forceinline__ void gemm_core(
    const float* __restrict__ xs,
    const float* __restrict__ Wl, const float* __restrict__ bl,
    const float* __restrict__ Wr, const float* __restrict__ br,
    __half* __restrict__ outl, __half* __restrict__ outr, int r0, int n)
{
    constexpr int QUADS = M / 2;          // (2M)/4 column quads
    const int t    = threadIdx.x;
    const int quad = t % QUADS;
    const int rg   = t / QUADS;           // warp-uniform
    const int c0   = quad * 4;
    const int mat  = (c0 >= M) ? 1 : 0;
    const int wc   = c0 & (M - 1);
    const int rb   = rg * 8;

    const float* __restrict__ W = mat ? Wr : Wl;

    u64 acc[8][4];
#pragma unroll
    for (int r = 0; r < 8; r++)
#pragma unroll
        for (int j = 0; j < 4; j++) acc[r][j] = 0ULL;

#pragma unroll 2
    for (int kp = 0; kp < K / 2; kp++) {
        const int k = 2 * kp;
        float4 wa = *(const float4*)&W[(size_t)k * M + wc];
        float4 wb = *(const float4*)&W[(size_t)(k + 1) * M + wc];
        u64 w0 = pack2(wa.x, wb.x);
        u64 w1 = pack2(wa.y, wb.y);
        u64 w2 = pack2(wa.z, wb.z);
        u64 w3 = pack2(wa.w, wb.w);
#pragma unroll
        for (int r = 0; r < 8; r++) {
            u64 xv = *(const u64*)&xs[(rb + r) * K + k];  // broadcast
            ffma2(acc[r][0], xv, w0);
            ffma2(acc[r][1], xv, w1);
            ffma2(acc[r][2], xv, w2);
            ffma2(acc[r][3], xv, w3);
        }
    }

    __half* __restrict__ out = mat ? outr : outl;
    const float* __restrict__ bs = mat ? br : bl;
    float4 bi = *(const float4*)&bs[wc];
#pragma unroll
    for (int r = 0; r < 8; r++) {
        int row = r0 + rb + r;
        if (row < n) {
            float2 a0 = unpack2(acc[r][0]);
            float2 a1 = unpack2(acc[r][1]);
            float2 a2 = unpack2(acc[r][2]);
            float2 a3 = unpack2(acc[r][3]);
            __half2* op = (__half2*)&out[(size_t)row * M + wc];
            op[0] = __floats2half2_rn(a0.x + a0.y + bi.x, a1.x + a1.y + bi.y);
            op[1] = __floats2half2_rn(a2.x + a2.y + bi.z, a3.x + a3.y + bi.w);
        }
    }
}

// ---------------- GEMM1: xl1/xr1 = x @ W1l/W1r + b (fp16 out) ----------------
__global__ __launch_bounds__(512, 1) void k_gemm1(
    const float* __restrict__ X,
    const float* __restrict__ Wl, const float* __restrict__ bl,
    const float* __restrict__ Wr, const float* __restrict__ br)
{
    extern __shared__ __align__(16) float xs[];      // [64][IN_CH]
    const int t  = threadIdx.x;
    const int r0 = blockIdx.x * 64;

    for (int i = t * 4; i < 64 * IN_CH; i += 512 * 4) {
        int row = i / IN_CH, kk = i % IN_CH;
        float4 v = make_float4(0.f, 0.f, 0.f, 0.f);
        if (r0 + row < NN) v = *(const float4*)&X[(size_t)(r0 + row) * IN_CH + kk];
        *(float4*)&xs[i] = v;
    }
    __syncthreads();

    gemm_core<IN_CH, C1>(xs, Wl, bl, Wr, br, g_xl1h, g_xr1h, r0, NN);
}

// ---------------- GEMM2 with FUSED layer-1 epilogue --------------------------
// Staging reads g_h1/g_sum1, applies /sum + bias + bn + elu into smem, and
// restores g_h1 to zero. g_sum1 is zeroed after staging (rows are exclusive
// to this block). No g_hm round-trip.
__global__ __launch_bounds__(256, 2) void k_gemm2(
    const float* __restrict__ Wl, const float* __restrict__ bl,
    const float* __restrict__ Wr, const float* __restrict__ br,
    const float* __restrict__ bias,
    const float* __restrict__ bg, const float* __restrict__ bb,
    const float* __restrict__ bm, const float* __restrict__ bv)
{
    extern __shared__ __align__(16) float xs[];      // [64][C1]
    const int t  = threadIdx.x;
    const int r0 = blockIdx.x * 64;

    for (int i = t * 4; i < 64 * C1; i += 256 * 4) {
        int row  = i / C1, kk = i % C1;
        int node = r0 + row;
        float4 o = make_float4(0.f, 0.f, 0.f, 0.f);
        if (node < NN) {
            float4 hv = *(const float4*)&g_h1[(size_t)node * C1 + kk];
            float inv_s = __fdividef(1.f, g_sum1[node * 2 + (kk >> 6)]);
            float4 bi = *(const float4*)&bias[kk];
            float4 gm = *(const float4*)&bg[kk];
            float4 bt = *(const float4*)&bb[kk];
            float4 mu = *(const float4*)&bm[kk];
            float4 vr = *(const float4*)&bv[kk];
            float x0 = (hv.x * inv_s + bi.x - mu.x) * rsqrtf(vr.x + BN_EPS) * gm.x + bt.x;
            float x1 = (hv.y * inv_s + bi.y - mu.y) * rsqrtf(vr.y + BN_EPS) * gm.y + bt.y;
            float x2 = (hv.z * inv_s + bi.z - mu.z) * rsqrtf(vr.z + BN_EPS) * gm.z + bt.z;
            float x3 = (hv.w * inv_s + bi.w - mu.w) * rsqrtf(vr.w + BN_EPS) * gm.w + bt.w;
            o.x = x0 > 0.f ? x0 : expm1f(x0);
            o.y = x1 > 0.f ? x1 : expm1f(x1);
            o.z = x2 > 0.f ? x2 : expm1f(x2);
            o.w = x3 > 0.f ? x3 : expm1f(x3);
            *(float4*)&g_h1[(size_t)node * C1 + kk] = make_float4(0.f, 0.f, 0.f, 0.f);
        }
        *(float4*)&xs[i] = o;
    }
    __syncthreads();

    // zero this block's g_sum1 entries (exclusively owned rows)
    if (t < 128) {
        int node = r0 + (t >> 1);
        if (node < NN) g_sum1[node * 2 + (t & 1)] = 0.f;
    }

    gemm_core<C1, HIDC>(xs, Wl, bl, Wr, br, g_xl2h, g_xr2h, r0, NN);
}

// ---------------- layer-1 FUSED edge pass (fp16 gathers, 16 lanes/edge) ------
__global__ void k_edge1(const int* __restrict__ ei, const float* __restrict__ att)
{
    int gid = blockIdx.x * blockDim.x + threadIdx.x;
    int e   = gid >> 4;                    // 16 lanes per edge
    int l   = gid & 15;
    if (e >= ETOT) return;

    int src, dst;
    if (e < EE) { src = ei[e]; dst = ei[EE + e]; }
    else        { src = dst = e - EE; }

    int ch = l * 8;
    uint4 ar = *(const uint4*)&g_xl1h[(size_t)src * C1 + ch];  // 8 halves
    uint4 br = *(const uint4*)&g_xr1h[(size_t)dst * C1 + ch];
    const __half2* ah = (const __half2*)&ar;
    const __half2* bh = (const __half2*)&br;

    float4 at0 = *(const float4*)&att[ch];
    float4 at1 = *(const float4*)&att[ch + 4];

    float2 a0 = __half22float2(ah[0]), a1 = __half22float2(ah[1]);
    float2 a2 = __half22float2(ah[2]), a3 = __half22float2(ah[3]);
    float2 b0 = __half22float2(bh[0]), b1 = __half22float2(bh[1]);
    float2 b2 = __half22float2(bh[2]), b3 = __half22float2(bh[3]);

    float s = at0.x * lrelu(a0.x + b0.x) + at0.y * lrelu(a0.y + b0.y)
            + at0.z * lrelu(a1.x + b1.x) + at0.w * lrelu(a1.y + b1.y)
            + at1.x * lrelu(a2.x + b2.x) + at1.y * lrelu(a2.y + b2.y)
            + at1.z * lrelu(a3.x + b3.x) + at1.w * lrelu(a3.y + b3.y);

    // reduce over each 8-lane half (one head each)
    s += __shfl_xor_sync(0xffffffffu, s, 4);
    s += __shfl_xor_sync(0xffffffffu, s, 2);
    s += __shfl_xor_sync(0xffffffffu, s, 1);

    float p = __expf(s);

    if ((l & 7) == 0)
        atomicAdd(&g_sum1[(size_t)dst * 2 + (l >> 3)], p);

    float4 v0 = make_float4(a0.x * p, a0.y * p, a1.x * p, a1.y * p);
    float4 v1 = make_float4(a2.x * p, a2.y * p, a3.x * p, a3.y * p);
    float* hb = &g_h1[(size_t)dst * C1 + ch];
    red_add_v4(hb,     v0);
    red_add_v4(hb + 4, v1);
}

// ---------------- layer-2 FUSED edge pass (fp16, 8 lanes/edge, 64ch) ---------
__global__ void k_edge2(const int* __restrict__ ei, const float* __restrict__ att)
{
    int gid = blockIdx.x * blockDim.x + threadIdx.x;
    int e   = gid >> 3;                    // 8 lanes per edge
    int l   = gid & 7;
    if (e >= ETOT) return;

    int src, dst;
    if (e < EE) { src = ei[e]; dst = ei[EE + e]; }
    else        { src = dst = e - EE; }

    int ch = l * 8;
    uint4 ar = *(const uint4*)&g_xl2h[(size_t)src * HIDC + ch];
    uint4 br = *(const uint4*)&g_xr2h[(size_t)dst * HIDC + ch];
    const __half2* ah = (const __half2*)&ar;
    const __half2* bh = (const __half2*)&br;

    float4 at0 = *(const float4*)&att[ch];
    float4 at1 = *(const float4*)&att[ch + 4];

    float2 a0 = __half22float2(ah[0]), a1 = __half22float2(ah[1]);
    float2 a2 = __half22float2(ah[2]), a3 = __half22float2(ah[3]);
    float2 b0 = __half22float2(bh[0]), b1 = __half22float2(bh[1]);
    float2 b2 = __half22float2(bh[2]), b3 = __half22float2(bh[3]);

    float s = at0.x * lrelu(a0.x + b0.x) + at0.y * lrelu(a0.y + b0.y)
            + at0.z * lrelu(a1.x + b1.x) + at0.w * lrelu(a1.y + b1.y)
            + at1.x * lrelu(a2.x + b2.x) + at1.y * lrelu(a2.y + b2.y)
            + at1.z * lrelu(a3.x + b3.x) + at1.w * lrelu(a3.y + b3.y);

    s += __shfl_xor_sync(0xffffffffu, s, 4);
    s += __shfl_xor_sync(0xffffffffu, s, 2);
    s += __shfl_xor_sync(0xffffffffu, s, 1);

    float p = __expf(s);

    if (l == 0)
        atomicAdd(&g_sum2[dst], p);

    float4 v0 = make_float4(a0.x * p, a0.y * p, a1.x * p, a1.y * p);
    float4 v1 = make_float4(a2.x * p, a2.y * p, a3.x * p, a3.y * p);
    float* hb = &g_h2[(size_t)dst * HIDC + ch];
    red_add_v4(hb,     v0);
    red_add_v4(hb + 4, v1);
}

// ---------------- final: /sum, +bias2, bn2, elu, classifier, sigmoid ---------
__global__ void k_final(const float* __restrict__ bias,
                        const float* __restrict__ bg, const float* __restrict__ bb,
                        const float* __restrict__ bm, const float* __restrict__ bv,
                        const float* __restrict__ Wc, const float* __restrict__ bc,
                        float* __restrict__ out)
{
    int warp = (blockIdx.x * blockDim.x + threadIdx.x) >> 5;
    int lane = threadIdx.x & 31;
    if (warp >= NN) return;

    float inv_s = __fdividef(1.f, g_sum2[warp]);
    int c = lane * 2;
    float2 h  = *(const float2*)&g_h2[(size_t)warp * HIDC + c];
    float x0 = h.x * inv_s + bias[c + 0];
    float x1 = h.y * inv_s + bias[c + 1];
    x0 = (x0 - bm[c + 0]) * rsqrtf(bv[c + 0] + BN_EPS) * bg[c + 0] + bb[c + 0];
    x1 = (x1 - bm[c + 1]) * rsqrtf(bv[c + 1] + BN_EPS) * bg[c + 1] + bb[c + 1];
    x0 = x0 > 0.f ? x0 : expm1f(x0);
    x1 = x1 > 0.f ? x1 : expm1f(x1);

    *(float2*)&g_h2[(size_t)warp * HIDC + c] = make_float2(0.f, 0.f);
    if (lane == 0) g_sum2[warp] = 0.f;

    float z = x0 * Wc[c + 0] + x1 * Wc[c + 1];
    z += __shfl_xor_sync(0xffffffffu, z, 16);
    z += __shfl_xor_sync(0xffffffffu, z, 8);
    z += __shfl_xor_sync(0xffffffffu, z, 4);
    z += __shfl_xor_sync(0xffffffffu, z, 2);
    z += __shfl_xor_sync(0xffffffffu, z, 1);

    if (lane == 0) {
        z += bc[0];
        out[warp] = 1.f / (1.f + __expf(-z));
    }
}

// ---------------- launch -----------------------------------------------------
extern "C" void kernel_launch(void* const* d_in, const int* in_sizes, int n_in,
                              void* d_out, int out_size)
{
    const float* x    = (const float*)d_in[0];
    const int*   ei   = (const int*)  d_in[1];
    const float* W1l  = (const float*)d_in[2];
    const float* b1l  = (const float*)d_in[3];
    const float* W1r  = (const float*)d_in[4];
    const float* b1r  = (const float*)d_in[5];
    const float* att1 = (const float*)d_in[6];
    const float* bias1= (const float*)d_in[7];
    const float* bn1g = (const float*)d_in[8];
    const float* bn1b = (const float*)d_in[9];
    const float* bn1m = (const float*)d_in[10];
    const float* bn1v = (const float*)d_in[11];
    const float* W2l  = (const float*)d_in[12];
    const float* b2l  = (const float*)d_in[13];
    const float* W2r  = (const float*)d_in[14];
    const float* b2r  = (const float*)d_in[15];
    const float* att2 = (const float*)d_in[16];
    const float* bias2= (const float*)d_in[17];
    const float* bn2g = (const float*)d_in[18];
    const float* bn2b = (const float*)d_in[19];
    const float* bn2m = (const float*)d_in[20];
    const float* bn2v = (const float*)d_in[21];
    const float* Wc   = (const float*)d_in[22];
    const float* bc   = (const float*)d_in[23];
    float* out = (float*)d_out;

    const int edge1Blocks = (ETOT * 16 + 255) / 256;   // 16 lanes per edge
    const int edge2Blocks = (ETOT * 8  + 255) / 256;   // 8 lanes per edge
    const int rowBlocks   = (NN + 63) / 64;            // 64-row tiles

    const int smem1 = 64 * IN_CH * sizeof(float);      // 64 KB
    const int smem2 = 64 * C1    * sizeof(float);      // 32 KB
    static bool attr_set = false;
    if (!attr_set) {
        cudaFuncSetAttribute(k_gemm1, cudaFuncAttributeMaxDynamicSharedMemorySize, smem1);
        cudaFuncSetAttribute(k_gemm2, cudaFuncAttributeMaxDynamicSharedMemorySize, smem2);
        attr_set = true;
    }

    // layer 1
    k_gemm1<<<rowBlocks, 512, smem1>>>(x, W1l, b1l, W1r, b1r);
    k_edge1<<<edge1Blocks, 256>>>(ei, att1);

    // layer 2 (epi1 fused into gemm2 staging)
    k_gemm2<<<rowBlocks, 256, smem2>>>(W2l, b2l, W2r, b2r,
                                       bias1, bn1g, bn1b, bn1m, bn1v);
    k_edge2<<<edge2Blocks, 256>>>(ei, att2);

    // epilogue + classifier
    k_final<<<(NN * 32 + 255) / 256, 256>>>(bias2, bn2g, bn2b, bn2m, bn2v, Wc, bc, out);
}

// round 11
// speedup vs baseline: 1.2275x; 1.2275x over previous
#include <cuda_runtime.h>
#include <cuda_fp16.h>
#include <cstdint>

#define NN      50000
#define EE      800000
#define ETOT    (EE + NN)        // edges + self loops
#define IN_CH   256
#define HIDC    64
#define HEADS   2
#define C1      (HEADS * HIDC)   // 128
#define BN_EPS  1e-5f

// ---------------- scratch (static device arrays; no allocation) --------------
__device__ __half g_xl1h[NN * C1];   // fp16 edge operands (gather traffic /2)
__device__ __half g_xr1h[NN * C1];
__device__ float  g_sum1[NN * HEADS];
__device__ float  g_h1 [NN * C1];    // layer-1: accumulates sum(p * xl), fp32
__device__ __half g_xl2h[NN * HIDC];
__device__ __half g_xr2h[NN * HIDC];
__device__ float  g_sum2[NN];
__device__ float  g_h2 [NN * HIDC];  // layer-2: accumulates sum(p * xl), fp32

// ---------------- helpers ----------------------------------------------------
typedef unsigned long long u64;

__device__ __forceinline__ float lrelu(float v) { return v > 0.f ? v : 0.2f * v; }

__device__ __forceinline__ void red_add_v4(float* addr, float4 v) {
    asm volatile("red.global.add.v4.f32 [%0], {%1, %2, %3, %4};"
                 :: "l"(addr), "f"(v.x), "f"(v.y), "f"(v.z), "f"(v.w) : "memory");
}

// packed f32x2 helpers (FFMA2 — only reachable via PTX on sm_103a)
__device__ __forceinline__ u64 bcast2(float w) {
    u64 r;
    asm("mov.b64 %0, {%1, %1};" : "=l"(r) : "f"(w));
    return r;
}
__device__ __forceinline__ void ffma2(u64& acc, u64 a, u64 b) {
    asm("fma.rn.f32x2 %0, %1, %2, %0;" : "+l"(acc) : "l"(a), "l"(b));
}
__device__ __forceinline__ float2 unpack2(u64 v) {
    float lo, hi;
    asm("mov.b64 {%0, %1}, %2;" : "=f"(lo), "=f"(hi) : "l"(v));
    return make_float2(lo, hi);
}

// ---------------- GEMM1 (R3 structure): xl1h/xr1h = x @ W1l/W1r + b ----------
// Tile: 32 rows x 2M cols. blockDim = M. Thread t owns 2 adjacent cols.
// X tile staged k-major in smem (pad 36). Row-pair packed FFMA2.
__global__ __launch_bounds__(C1) void k_gemm1(
    const float* __restrict__ X,
    const float* __restrict__ Wl, const float* __restrict__ bl,
    const float* __restrict__ Wr, const float* __restrict__ br)
{
    constexpr int K = IN_CH, M = C1, PAD = 36;
    __shared__ __align__(16) float xs[K * PAD];   // xs[k*PAD + row]
    const int t  = threadIdx.x;                   // 0..M-1
    const int r0 = blockIdx.x * 32;

    for (int i = t * 4; i < 32 * K; i += M * 4) {
        int row = i / K, kk = i % K;
        float4 v = make_float4(0.f, 0.f, 0.f, 0.f);
        if (r0 + row < NN) v = *(const float4*)&X[(size_t)(r0 + row) * K + kk];
        xs[(kk + 0) * PAD + row] = v.x;
        xs[(kk + 1) * PAD + row] = v.y;
        xs[(kk + 2) * PAD + row] = v.z;
        xs[(kk + 3) * PAD + row] = v.w;
    }
    __syncthreads();

    const int c0  = 2 * t;
    const int mat = (c0 >= M) ? 1 : 0;
    const float* __restrict__ W  = mat ? (const float*)Wr : (const float*)Wl;
    const float* __restrict__ bs = mat ? br : bl;
    const int wc = c0 & (M - 1);

    u64 accA[16], accB[16];
#pragma unroll
    for (int r = 0; r < 16; r++) { accA[r] = 0ULL; accB[r] = 0ULL; }

#pragma unroll 4
    for (int k = 0; k < K; k++) {
        float2 w = *(const float2*)&W[k * M + wc];
        u64 wA = bcast2(w.x);
        u64 wB = bcast2(w.y);
        const u64* xrow = (const u64*)&xs[k * PAD];
#pragma unroll
        for (int r = 0; r < 16; r++) {
            u64 xv = xrow[r];
            ffma2(accA[r], xv, wA);
            ffma2(accB[r], xv, wB);
        }
    }

    __half* __restrict__ out = mat ? g_xr1h : g_xl1h;
    const float b0 = bs[wc], b1 = bs[wc + 1];
#pragma unroll
    for (int r = 0; r < 16; r++) {
        float2 a = unpack2(accA[r]);
        float2 b = unpack2(accB[r]);
        int row = r0 + 2 * r;
        if (row < NN)
            *(__half2*)&out[(size_t)row * M + wc] =
                __floats2half2_rn(a.x + b0, b.x + b1);
        if (row + 1 < NN)
            *(__half2*)&out[(size_t)(row + 1) * M + wc] =
                __floats2half2_rn(a.y + b0, b.y + b1);
    }
}

// ---------------- GEMM2 with FUSED layer-1 epilogue (R3 structure) -----------
// Staging reads g_h1/g_sum1, applies /sum + bias + bn + elu while transposing
// into smem, and restores g_h1 to zero. g_sum1 is zeroed AFTER the barrier
// (all staging reads done), rows exclusive to this block.
__global__ __launch_bounds__(HIDC) void k_gemm2(
    const float* __restrict__ Wl, const float* __restrict__ bl,
    const float* __restrict__ Wr, const float* __restrict__ br,
    const float* __restrict__ bias,
    const float* __restrict__ bg, const float* __restrict__ bb,
    const float* __restrict__ bm, const float* __restrict__ bv)
{
    constexpr int K = C1, M = HIDC, PAD = 36;
    __shared__ __align__(16) float xs[K * PAD];   // xs[k*PAD + row]
    const int t  = threadIdx.x;                   // 0..M-1
    const int r0 = blockIdx.x * 32;

    for (int i = t * 4; i < 32 * K; i += M * 4) {
        int row  = i / K, kk = i % K;
        int node = r0 + row;
        float4 o = make_float4(0.f, 0.f, 0.f, 0.f);
        if (node < NN) {
            float4 hv = *(const float4*)&g_h1[(size_t)node * K + kk];
            float inv_s = __fdividef(1.f, g_sum1[node * 2 + (kk >> 6)]);
            float4 bi = *(const float4*)&bias[kk];
            float4 gm = *(const float4*)&bg[kk];
            float4 bt = *(const float4*)&bb[kk];
            float4 mu = *(const float4*)&bm[kk];
            float4 vr = *(const float4*)&bv[kk];
            float x0 = (hv.x * inv_s + bi.x - mu.x) * rsqrtf(vr.x + BN_EPS) * gm.x + bt.x;
            float x1 = (hv.y * inv_s + bi.y - mu.y) * rsqrtf(vr.y + BN_EPS) * gm.y + bt.y;
            float x2 = (hv.z * inv_s + bi.z - mu.z) * rsqrtf(vr.z + BN_EPS) * gm.z + bt.z;
            float x3 = (hv.w * inv_s + bi.w - mu.w) * rsqrtf(vr.w + BN_EPS) * gm.w + bt.w;
            o.x = x0 > 0.f ? x0 : expm1f(x0);
            o.y = x1 > 0.f ? x1 : expm1f(x1);
            o.z = x2 > 0.f ? x2 : expm1f(x2);
            o.w = x3 > 0.f ? x3 : expm1f(x3);
            *(float4*)&g_h1[(size_t)node * K + kk] = make_float4(0.f, 0.f, 0.f, 0.f);
        }
        xs[(kk + 0) * PAD + row] = o.x;
        xs[(kk + 1) * PAD + row] = o.y;
        xs[(kk + 2) * PAD + row] = o.z;
        xs[(kk + 3) * PAD + row] = o.w;
    }
    __syncthreads();   // ALL staging reads of g_sum1 complete here

    // zero this block's g_sum1 entries (rows exclusively owned by this block);
    // must come AFTER the barrier so no sibling thread still reads them.
    {
        int node = r0 + (t >> 1);
        if (node < NN) g_sum1[node * 2 + (t & 1)] = 0.f;   // t<64 covers 32 rows
    }

    const int c0  = 2 * t;
    const int mat = (c0 >= M) ? 1 : 0;
    const float* __restrict__ W  = mat ? Wr : Wl;
    const float* __restrict__ bs = mat ? br : bl;
    const int wc = c0 & (M - 1);

    u64 accA[16], accB[16];
#pragma unroll
    for (int r = 0; r < 16; r++) { accA[r] = 0ULL; accB[r] = 0ULL; }

#pragma unroll 4
    for (int k = 0; k < K; k++) {
        float2 w = *(const float2*)&W[k * M + wc];
        u64 wA = bcast2(w.x);
        u64 wB = bcast2(w.y);
        const u64* xrow = (const u64*)&xs[k * PAD];
#pragma unroll
        for (int r = 0; r < 16; r++) {
            u64 xv = xrow[r];
            ffma2(accA[r], xv, wA);
            ffma2(accB[r], xv, wB);
        }
    }

    __half* __restrict__ out = mat ? g_xr2h : g_xl2h;
    const float b0 = bs[wc], b1 = bs[wc + 1];
#pragma unroll
    for (int r = 0; r < 16; r++) {
        float2 a = unpack2(accA[r]);
        float2 b = unpack2(accB[r]);
        int row = r0 + 2 * r;
        if (row < NN)
            *(__half2*)&out[(size_t)row * M + wc] =
                __floats2half2_rn(a.x + b0, b.x + b1);
        if (row + 1 < NN)
            *(__half2*)&out[(size_t)(row + 1) * M + wc] =
                __floats2half2_rn(a.y + b0, b.y + b1);
    }
}

// ---------------- layer-1 FUSED edge pass (fp16 gathers, 16 lanes/edge) ------
__global__ void k_edge1(const int* __restrict__ ei, const float* __restrict__ att)
{
    int gid = blockIdx.x * blockDim.x + threadIdx.x;
    int e   = gid >> 4;                    // 16 lanes per edge
    int l   = gid & 15;
    if (e >= ETOT) return;

    int src, dst;
    if (e < EE) { src = ei[e]; dst = ei[EE + e]; }
    else        { src = dst = e - EE; }

    int ch = l * 8;
    uint4 ar = *(const uint4*)&g_xl1h[(size_t)src * C1 + ch];  // 8 halves
    uint4 br = *(const uint4*)&g_xr1h[(size_t)dst * C1 + ch];
    const __half2* ah = (const __half2*)&ar;
    const __half2* bh = (const __half2*)&br;

    float4 at0 = *(const float4*)&att[ch];
    float4 at1 = *(const float4*)&att[ch + 4];

    float2 a0 = __half22float2(ah[0]), a1 = __half22float2(ah[1]);
    float2 a2 = __half22float2(ah[2]), a3 = __half22float2(ah[3]);
    float2 b0 = __half22float2(bh[0]), b1 = __half22float2(bh[1]);
    float2 b2 = __half22float2(bh[2]), b3 = __half22float2(bh[3]);

    float s = at0.x * lrelu(a0.x + b0.x) + at0.y * lrelu(a0.y + b0.y)
            + at0.z * lrelu(a1.x + b1.x) + at0.w * lrelu(a1.y + b1.y)
            + at1.x * lrelu(a2.x + b2.x) + at1.y * lrelu(a2.y + b2.y)
            + at1.z * lrelu(a3.x + b3.x) + at1.w * lrelu(a3.y + b3.y);

    // reduce over each 8-lane half (one head each)
    s += __shfl_xor_sync(0xffffffffu, s, 4);
    s += __shfl_xor_sync(0xffffffffu, s, 2);
    s += __shfl_xor_sync(0xffffffffu, s, 1);

    float p = __expf(s);

    if ((l & 7) == 0)
        atomicAdd(&g_sum1[(size_t)dst * 2 + (l >> 3)], p);

    float4 v0 = make_float4(a0.x * p, a0.y * p, a1.x * p, a1.y * p);
    float4 v1 = make_float4(a2.x * p, a2.y * p, a3.x * p, a3.y * p);
    float* hb = &g_h1[(size_t)dst * C1 + ch];
    red_add_v4(hb,     v0);
    red_add_v4(hb + 4, v1);
}

// ---------------- layer-2 FUSED edge pass (fp16, 8 lanes/edge, 64ch) ---------
__global__ void k_edge2(const int* __restrict__ ei, const float* __restrict__ att)
{
    int gid = blockIdx.x * blockDim.x + threadIdx.x;
    int e   = gid >> 3;                    // 8 lanes per edge
    int l   = gid & 7;
    if (e >= ETOT) return;

    int src, dst;
    if (e < EE) { src = ei[e]; dst = ei[EE + e]; }
    else        { src = dst = e - EE; }

    int ch = l * 8;
    uint4 ar = *(const uint4*)&g_xl2h[(size_t)src * HIDC + ch];
    uint4 br = *(const uint4*)&g_xr2h[(size_t)dst * HIDC + ch];
    const __half2* ah = (const __half2*)&ar;
    const __half2* bh = (const __half2*)&br;

    float4 at0 = *(const float4*)&att[ch];
    float4 at1 = *(const float4*)&att[ch + 4];

    float2 a0 = __half22float2(ah[0]), a1 = __half22float2(ah[1]);
    float2 a2 = __half22float2(ah[2]), a3 = __half22float2(ah[3]);
    float2 b0 = __half22float2(bh[0]), b1 = __half22float2(bh[1]);
    float2 b2 = __half22float2(bh[2]), b3 = __half22float2(bh[3]);

    float s = at0.x * lrelu(a0.x + b0.x) + at0.y * lrelu(a0.y + b0.y)
            + at0.z * lrelu(a1.x + b1.x) + at0.w * lrelu(a1.y + b1.y)
            + at1.x * lrelu(a2.x + b2.x) + at1.y * lrelu(a2.y + b2.y)
            + at1.z * lrelu(a3.x + b3.x) + at1.w * lrelu(a3.y + b3.y);

    s += __shfl_xor_sync(0xffffffffu, s, 4);
    s += __shfl_xor_sync(0xffffffffu, s, 2);
    s += __shfl_xor_sync(0xffffffffu, s, 1);

    float p = __expf(s);

    if (l == 0)
        atomicAdd(&g_sum2[dst], p);

    float4 v0 = make_float4(a0.x * p, a0.y * p, a1.x * p, a1.y * p);
    float4 v1 = make_float4(a2.x * p, a2.y * p, a3.x * p, a3.y * p);
    float* hb = &g_h2[(size_t)dst * HIDC + ch];
    red_add_v4(hb,     v0);
    red_add_v4(hb + 4, v1);
}

// ---------------- final: /sum, +bias2, bn2, elu, classifier, sigmoid ---------
// Restores g_h2 / g_sum2 to zero (warp-private, program-order safe).
__global__ void k_final(const float* __restrict__ bias,
                        const float* __restrict__ bg, const float* __restrict__ bb,
                        const float* __restrict__ bm, const float* __restrict__ bv,
                        const float* __restrict__ Wc, const float* __restrict__ bc,
                        float* __restrict__ out)
{
    int warp = (blockIdx.x * blockDim.x + threadIdx.x) >> 5;
    int lane = threadIdx.x & 31;
    if (warp >= NN) return;

    float inv_s = __fdividef(1.f, g_sum2[warp]);
    int c = lane * 2;
    float2 h  = *(const float2*)&g_h2[(size_t)warp * HIDC + c];
    float x0 = h.x * inv_s + bias[c + 0];
    float x1 = h.y * inv_s + bias[c + 1];
    x0 = (x0 - bm[c + 0]) * rsqrtf(bv[c + 0] + BN_EPS) * bg[c + 0] + bb[c + 0];
    x1 = (x1 - bm[c + 1]) * rsqrtf(bv[c + 1] + BN_EPS) * bg[c + 1] + bb[c + 1];
    x0 = x0 > 0.f ? x0 : expm1f(x0);
    x1 = x1 > 0.f ? x1 : expm1f(x1);

    *(float2*)&g_h2[(size_t)warp * HIDC + c] = make_float2(0.f, 0.f);
    if (lane == 0) g_sum2[warp] = 0.f;

    float z = x0 * Wc[c + 0] + x1 * Wc[c + 1];
    z += __shfl_xor_sync(0xffffffffu, z, 16);
    z += __shfl_xor_sync(0xffffffffu, z, 8);
    z += __shfl_xor_sync(0xffffffffu, z, 4);
    z += __shfl_xor_sync(0xffffffffu, z, 2);
    z += __shfl_xor_sync(0xffffffffu, z, 1);

    if (lane == 0) {
        z += bc[0];
        out[warp] = 1.f / (1.f + __expf(-z));
    }
}

// ---------------- launch -----------------------------------------------------
extern "C" void kernel_launch(void* const* d_in, const int* in_sizes, int n_in,
                              void* d_out, int out_size)
{
    const float* x    = (const float*)d_in[0];
    const int*   ei   = (const int*)  d_in[1];
    const float* W1l  = (const float*)d_in[2];
    const float* b1l  = (const float*)d_in[3];
    const float* W1r  = (const float*)d_in[4];
    const float* b1r  = (const float*)d_in[5];
    const float* att1 = (const float*)d_in[6];
    const float* bias1= (const float*)d_in[7];
    const float* bn1g = (const float*)d_in[8];
    const float* bn1b = (const float*)d_in[9];
    const float* bn1m = (const float*)d_in[10];
    const float* bn1v = (const float*)d_in[11];
    const float* W2l  = (const float*)d_in[12];
    const float* b2l  = (const float*)d_in[13];
    const float* W2r  = (const float*)d_in[14];
    const float* b2r  = (const float*)d_in[15];
    const float* att2 = (const float*)d_in[16];
    const float* bias2= (const float*)d_in[17];
    const float* bn2g = (const float*)d_in[18];
    const float* bn2b = (const float*)d_in[19];
    const float* bn2m = (const float*)d_in[20];
    const float* bn2v = (const float*)d_in[21];
    const float* Wc   = (const float*)d_in[22];
    const float* bc   = (const float*)d_in[23];
    float* out = (float*)d_out;

    const int edge1Blocks = (ETOT * 16 + 255) / 256;   // 16 lanes per edge
    const int edge2Blocks = (ETOT * 8  + 255) / 256;   // 8 lanes per edge
    const int rowBlocks   = (NN + 31) / 32;            // 32-row tiles

    // layer 1
    k_gemm1<<<rowBlocks, C1>>>(x, W1l, b1l, W1r, b1r);
    k_edge1<<<edge1Blocks, 256>>>(ei, att1);

    // layer 2 (layer-1 epilogue fused into gemm2 staging)
    k_gemm2<<<rowBlocks, HIDC>>>(W2l, b2l, W2r, b2r,
                                 bias1, bn1g, bn1b, bn1m, bn1v);
    k_edge2<<<edge2Blocks, 256>>>(ei, att2);

    // epilogue + classifier
    k_final<<<(NN * 32 + 255) / 256, 256>>>(bias2, bn2g, bn2b, bn2m, bn2v, Wc, bc, out);
}

// round 12
// speedup vs baseline: 1.3180x; 1.0737x over previous
#include <cuda_runtime.h>
#include <cuda_fp16.h>
#include <cstdint>

#define NN      50000
#define EE      800000
#define ETOT    (EE + NN)        // edges + self loops (850000, even)
#define IN_CH   256
#define HIDC    64
#define HEADS   2
#define C1      (HEADS * HIDC)   // 128
#define BN_EPS  1e-5f

// ---------------- scratch (static device arrays; no allocation) --------------
__device__ __half g_xl1h[NN * C1];   // fp16 edge operands (gather traffic /2)
__device__ __half g_xr1h[NN * C1];
__device__ float  g_sum1[NN * HEADS];
__device__ float  g_h1 [NN * C1];    // layer-1: accumulates sum(p * xl), fp32
__device__ float  g_hm [NN * C1];    // after bn1 + elu
__device__ __half g_xl2h[NN * HIDC];
__device__ __half g_xr2h[NN * HIDC];
__device__ float  g_sum2[NN];
__device__ float  g_h2 [NN * HIDC];  // layer-2: accumulates sum(p * xl), fp32

// ---------------- helpers ----------------------------------------------------
typedef unsigned long long u64;

__device__ __forceinline__ float lrelu(float v) { return v > 0.f ? v : 0.2f * v; }

__device__ __forceinline__ void red_add_v4(float* addr, float4 v) {
    asm volatile("red.global.add.v4.f32 [%0], {%1, %2, %3, %4};"
                 :: "l"(addr), "f"(v.x), "f"(v.y), "f"(v.z), "f"(v.w) : "memory");
}

// packed f32x2 helpers (FFMA2 — only reachable via PTX on sm_103a)
__device__ __forceinline__ u64 bcast2(float w) {
    u64 r;
    asm("mov.b64 %0, {%1, %1};" : "=l"(r) : "f"(w));
    return r;
}
__device__ __forceinline__ void ffma2(u64& acc, u64 a, u64 b) {
    asm("fma.rn.f32x2 %0, %1, %2, %0;" : "+l"(acc) : "l"(a), "l"(b));
}
__device__ __forceinline__ float2 unpack2(u64 v) {
    float lo, hi;
    asm("mov.b64 {%0, %1}, %2;" : "=f"(lo), "=f"(hi) : "l"(v));
    return make_float2(lo, hi);
}

// logit contribution for 8 fp16 channel-pairs vs att coefficients
__device__ __forceinline__ float logit8(uint4 ar, uint4 br, float4 at0, float4 at1)
{
    const __half2* ah = (const __half2*)&ar;
    const __half2* bh = (const __half2*)&br;
    float2 a0 = __half22float2(ah[0]), a1 = __half22float2(ah[1]);
    float2 a2 = __half22float2(ah[2]), a3 = __half22float2(ah[3]);
    float2 b0 = __half22float2(bh[0]), b1 = __half22float2(bh[1]);
    float2 b2 = __half22float2(bh[2]), b3 = __half22float2(bh[3]);
    return at0.x * lrelu(a0.x + b0.x) + at0.y * lrelu(a0.y + b0.y)
         + at0.z * lrelu(a1.x + b1.x) + at0.w * lrelu(a1.y + b1.y)
         + at1.x * lrelu(a2.x + b2.x) + at1.y * lrelu(a2.y + b2.y)
         + at1.z * lrelu(a3.x + b3.x) + at1.w * lrelu(a3.y + b3.y);
}

// scale 8 fp16 channels by p -> two float4
__device__ __forceinline__ void scale8(uint4 ar, float p, float4& v0, float4& v1)
{
    const __half2* ah = (const __half2*)&ar;
    float2 a0 = __half22float2(ah[0]), a1 = __half22float2(ah[1]);
    float2 a2 = __half22float2(ah[2]), a3 = __half22float2(ah[3]);
    v0 = make_float4(a0.x * p, a0.y * p, a1.x * p, a1.y * p);
    v1 = make_float4(a2.x * p, a2.y * p, a3.x * p, a3.y * p);
}

// ---------------- GEMM1 (R3 structure): xl1h/xr1h = x @ W1l/W1r + b ----------
__global__ __launch_bounds__(C1) void k_gemm1(
    const float* __restrict__ X,
    const float* __restrict__ Wl, const float* __restrict__ bl,
    const float* __restrict__ Wr, const float* __restrict__ br)
{
    constexpr int K = IN_CH, M = C1, PAD = 36;
    __shared__ __align__(16) float xs[K * PAD];   // xs[k*PAD + row]
    const int t  = threadIdx.x;                   // 0..M-1
    const int r0 = blockIdx.x * 32;

    for (int i = t * 4; i < 32 * K; i += M * 4) {
        int row = i / K, kk = i % K;
        float4 v = make_float4(0.f, 0.f, 0.f, 0.f);
        if (r0 + row < NN) v = *(const float4*)&X[(size_t)(r0 + row) * K + kk];
        xs[(kk + 0) * PAD + row] = v.x;
        xs[(kk + 1) * PAD + row] = v.y;
        xs[(kk + 2) * PAD + row] = v.z;
        xs[(kk + 3) * PAD + row] = v.w;
    }
    __syncthreads();

    const int c0  = 2 * t;
    const int mat = (c0 >= M) ? 1 : 0;
    const float* __restrict__ W  = mat ? Wr : Wl;
    const float* __restrict__ bs = mat ? br : bl;
    const int wc = c0 & (M - 1);

    u64 accA[16], accB[16];
#pragma unroll
    for (int r = 0; r < 16; r++) { accA[r] = 0ULL; accB[r] = 0ULL; }

#pragma unroll 4
    for (int k = 0; k < K; k++) {
        float2 w = *(const float2*)&W[k * M + wc];
        u64 wA = bcast2(w.x);
        u64 wB = bcast2(w.y);
        const u64* xrow = (const u64*)&xs[k * PAD];
#pragma unroll
        for (int r = 0; r < 16; r++) {
            u64 xv = xrow[r];
            ffma2(accA[r], xv, wA);
            ffma2(accB[r], xv, wB);
        }
    }

    __half* __restrict__ out = mat ? g_xr1h : g_xl1h;
    const float b0 = bs[wc], b1 = bs[wc + 1];
#pragma unroll
    for (int r = 0; r < 16; r++) {
        float2 a = unpack2(accA[r]);
        float2 b = unpack2(accB[r]);
        int row = r0 + 2 * r;
        if (row < NN)
            *(__half2*)&out[(size_t)row * M + wc] =
                __floats2half2_rn(a.x + b0, b.x + b1);
        if (row + 1 < NN)
            *(__half2*)&out[(size_t)(row + 1) * M + wc] =
                __floats2half2_rn(a.y + b0, b.y + b1);
    }
}

// ---------------- GEMM2 (R3 structure), reads g_hm, zeros g_sum1 -------------
__global__ __launch_bounds__(HIDC) void k_gemm2(
    const float* __restrict__ Wl, const float* __restrict__ bl,
    const float* __restrict__ Wr, const float* __restrict__ br)
{
    constexpr int K = C1, M = HIDC, PAD = 36;
    __shared__ __align__(16) float xs[K * PAD];   // xs[k*PAD + row]
    const int t  = threadIdx.x;                   // 0..M-1
    const int r0 = blockIdx.x * 32;

    // zero this block's g_sum1 entries (consumed by k_epi1 earlier; next
    // reader is edge1 of the NEXT launch — race-free)
    {
        int node = r0 + (t >> 1);
        if (node < NN) g_sum1[node * 2 + (t & 1)] = 0.f;   // t<64 covers 32 rows
    }

    for (int i = t * 4; i < 32 * K; i += M * 4) {
        int row = i / K, kk = i % K;
        float4 v = make_float4(0.f, 0.f, 0.f, 0.f);
        if (r0 + row < NN) v = *(const float4*)&g_hm[(size_t)(r0 + row) * K + kk];
        xs[(kk + 0) * PAD + row] = v.x;
        xs[(kk + 1) * PAD + row] = v.y;
        xs[(kk + 2) * PAD + row] = v.z;
        xs[(kk + 3) * PAD + row] = v.w;
    }
    __syncthreads();

    const int c0  = 2 * t;
    const int mat = (c0 >= M) ? 1 : 0;
    const float* __restrict__ W  = mat ? Wr : Wl;
    const float* __restrict__ bs = mat ? br : bl;
    const int wc = c0 & (M - 1);

    u64 accA[16], accB[16];
#pragma unroll
    for (int r = 0; r < 16; r++) { accA[r] = 0ULL; accB[r] = 0ULL; }

#pragma unroll 4
    for (int k = 0; k < K; k++) {
        float2 w = *(const float2*)&W[k * M + wc];
        u64 wA = bcast2(w.x);
        u64 wB = bcast2(w.y);
        const u64* xrow = (const u64*)&xs[k * PAD];
#pragma unroll
        for (int r = 0; r < 16; r++) {
            u64 xv = xrow[r];
            ffma2(accA[r], xv, wA);
            ffma2(accB[r], xv, wB);
        }
    }

    __half* __restrict__ out = mat ? g_xr2h : g_xl2h;
    const float b0 = bs[wc], b1 = bs[wc + 1];
#pragma unroll
    for (int r = 0; r < 16; r++) {
        float2 a = unpack2(accA[r]);
        float2 b = unpack2(accB[r]);
        int row = r0 + 2 * r;
        if (row < NN)
            *(__half2*)&out[(size_t)row * M + wc] =
                __floats2half2_rn(a.x + b0, b.x + b1);
        if (row + 1 < NN)
            *(__half2*)&out[(size_t)(row + 1) * M + wc] =
                __floats2half2_rn(a.y + b0, b.y + b1);
    }
}

// ---------------- layer-1 FUSED edge pass: 2 edges per thread ----------------
// group of 16 lanes handles edges (2g, 2g+1); lane l owns 8 channels.
// Pairs never straddle the EE boundary (EE even, pairs aligned).
__global__ void k_edge1(const int* __restrict__ ei, const float* __restrict__ att)
{
    int gid = blockIdx.x * blockDim.x + threadIdx.x;
    int g   = gid >> 4;                    // 16 lanes per edge PAIR
    int l   = gid & 15;
    int e0  = g * 2;
    if (e0 >= ETOT) return;

    int src0, dst0, src1, dst1;
    if (e0 < EE) {
        int2 sp = *(const int2*)&ei[e0];         // 8B aligned (e0 even)
        int2 dp = *(const int2*)&ei[EE + e0];    // EE even
        src0 = sp.x; src1 = sp.y; dst0 = dp.x; dst1 = dp.y;
    } else {
        src0 = dst0 = e0 - EE;
        src1 = dst1 = e0 + 1 - EE;
    }

    int ch = l * 8;
    // four independent gathers issued before any consume (MLP = 4)
    uint4 ar0 = *(const uint4*)&g_xl1h[(size_t)src0 * C1 + ch];
    uint4 br0 = *(const uint4*)&g_xr1h[(size_t)dst0 * C1 + ch];
    uint4 ar1 = *(const uint4*)&g_xl1h[(size_t)src1 * C1 + ch];
    uint4 br1 = *(const uint4*)&g_xr1h[(size_t)dst1 * C1 + ch];

    float4 at0 = *(const float4*)&att[ch];
    float4 at1 = *(const float4*)&att[ch + 4];

    float s0 = logit8(ar0, br0, at0, at1);
    float s1 = logit8(ar1, br1, at0, at1);

    // reduce over each 8-lane half (one head each), both edges together
    s0 += __shfl_xor_sync(0xffffffffu, s0, 4);
    s1 += __shfl_xor_sync(0xffffffffu, s1, 4);
    s0 += __shfl_xor_sync(0xffffffffu, s0, 2);
    s1 += __shfl_xor_sync(0xffffffffu, s1, 2);
    s0 += __shfl_xor_sync(0xffffffffu, s0, 1);
    s1 += __shfl_xor_sync(0xffffffffu, s1, 1);

    float p0 = __expf(s0);
    float p1 = __expf(s1);

    if ((l & 7) == 0) {
        int h = l >> 3;
        atomicAdd(&g_sum1[(size_t)dst0 * 2 + h], p0);
        atomicAdd(&g_sum1[(size_t)dst1 * 2 + h], p1);
    }

    float4 v0, v1;
    scale8(ar0, p0, v0, v1);
    float* hb0 = &g_h1[(size_t)dst0 * C1 + ch];
    red_add_v4(hb0,     v0);
    red_add_v4(hb0 + 4, v1);

    scale8(ar1, p1, v0, v1);
    float* hb1 = &g_h1[(size_t)dst1 * C1 + ch];
    red_add_v4(hb1,     v0);
    red_add_v4(hb1 + 4, v1);
}

// ---------------- layer-1 epilogue: /sum, +bias, bn, elu (float4) ------------
// Restores g_h1 to zero for next graph replay.
__global__ void k_epi1(const float* __restrict__ bias,
                       const float* __restrict__ bg, const float* __restrict__ bb,
                       const float* __restrict__ bm, const float* __restrict__ bv)
{
    int i4 = (blockIdx.x * blockDim.x + threadIdx.x) * 4;
    if (i4 >= NN * C1) return;
    int c    = i4 & (C1 - 1);
    int node = i4 >> 7;                   // C1 == 128
    int h    = c >> 6;
    float inv_s = __fdividef(1.f, g_sum1[node * 2 + h]);

    float4 hv = *(const float4*)&g_h1[i4];
    float4 bi = *(const float4*)&bias[c];
    float4 gm = *(const float4*)&bg[c];
    float4 bt = *(const float4*)&bb[c];
    float4 mu = *(const float4*)&bm[c];
    float4 vr = *(const float4*)&bv[c];

    float x0 = (hv.x * inv_s + bi.x - mu.x) * rsqrtf(vr.x + BN_EPS) * gm.x + bt.x;
    float x1 = (hv.y * inv_s + bi.y - mu.y) * rsqrtf(vr.y + BN_EPS) * gm.y + bt.y;
    float x2 = (hv.z * inv_s + bi.z - mu.z) * rsqrtf(vr.z + BN_EPS) * gm.z + bt.z;
    float x3 = (hv.w * inv_s + bi.w - mu.w) * rsqrtf(vr.w + BN_EPS) * gm.w + bt.w;

    float4 o;
    o.x = x0 > 0.f ? x0 : expm1f(x0);
    o.y = x1 > 0.f ? x1 : expm1f(x1);
    o.z = x2 > 0.f ? x2 : expm1f(x2);
    o.w = x3 > 0.f ? x3 : expm1f(x3);
    *(float4*)&g_hm[i4] = o;
    *(float4*)&g_h1[i4] = make_float4(0.f, 0.f, 0.f, 0.f);
}

// ---------------- layer-2 FUSED edge pass: 2 edges per thread ----------------
// group of 8 lanes handles edges (2g, 2g+1); lane l owns 8 channels (64 total).
__global__ void k_edge2(const int* __restrict__ ei, const float* __restrict__ att)
{
    int gid = blockIdx.x * blockDim.x + threadIdx.x;
    int g   = gid >> 3;                    // 8 lanes per edge PAIR
    int l   = gid & 7;
    int e0  = g * 2;
    if (e0 >= ETOT) return;

    int src0, dst0, src1, dst1;
    if (e0 < EE) {
        int2 sp = *(const int2*)&ei[e0];
        int2 dp = *(const int2*)&ei[EE + e0];
        src0 = sp.x; src1 = sp.y; dst0 = dp.x; dst1 = dp.y;
    } else {
        src0 = dst0 = e0 - EE;
        src1 = dst1 = e0 + 1 - EE;
    }

    int ch = l * 8;
    uint4 ar0 = *(const uint4*)&g_xl2h[(size_t)src0 * HIDC + ch];
    uint4 br0 = *(const uint4*)&g_xr2h[(size_t)dst0 * HIDC + ch];
    uint4 ar1 = *(const uint4*)&g_xl2h[(size_t)src1 * HIDC + ch];
    uint4 br1 = *(const uint4*)&g_xr2h[(size_t)dst1 * HIDC + ch];

    float4 at0 = *(const float4*)&att[ch];
    float4 at1 = *(const float4*)&att[ch + 4];

    float s0 = logit8(ar0, br0, at0, at1);
    float s1 = logit8(ar1, br1, at0, at1);

    s0 += __shfl_xor_sync(0xffffffffu, s0, 4);
    s1 += __shfl_xor_sync(0xffffffffu, s1, 4);
    s0 += __shfl_xor_sync(0xffffffffu, s0, 2);
    s1 += __shfl_xor_sync(0xffffffffu, s1, 2);
    s0 += __shfl_xor_sync(0xffffffffu, s0, 1);
    s1 += __shfl_xor_sync(0xffffffffu, s1, 1);

    float p0 = __expf(s0);
    float p1 = __expf(s1);

    if (l == 0) {
        atomicAdd(&g_sum2[dst0], p0);
        atomicAdd(&g_sum2[dst1], p1);
    }

    float4 v0, v1;
    scale8(ar0, p0, v0, v1);
    float* hb0 = &g_h2[(size_t)dst0 * HIDC + ch];
    red_add_v4(hb0,     v0);
    red_add_v4(hb0 + 4, v1);

    scale8(ar1, p1, v0, v1);
    float* hb1 = &g_h2[(size_t)dst1 * HIDC + ch];
    red_add_v4(hb1,     v0);
    red_add_v4(hb1 + 4, v1);
}

// ---------------- final: /sum, +bias2, bn2, elu, classifier, sigmoid ---------
// Restores g_h2 / g_sum2 to zero (warp-private, program-order safe).
__global__ void k_final(const float* __restrict__ bias,
                        const float* __restrict__ bg, const float* __restrict__ bb,
                        const float* __restrict__ bm, const float* __restrict__ bv,
                        const float* __restrict__ Wc, const float* __restrict__ bc,
                        float* __restrict__ out)
{
    int warp = (blockIdx.x * blockDim.x + threadIdx.x) >> 5;
    int lane = threadIdx.x & 31;
    if (warp >= NN) return;

    float inv_s = __fdividef(1.f, g_sum2[warp]);
    int c = lane * 2;
    float2 h  = *(const float2*)&g_h2[(size_t)warp * HIDC + c];
    float x0 = h.x * inv_s + bias[c + 0];
    float x1 = h.y * inv_s + bias[c + 1];
    x0 = (x0 - bm[c + 0]) * rsqrtf(bv[c + 0] + BN_EPS) * bg[c + 0] + bb[c + 0];
    x1 = (x1 - bm[c + 1]) * rsqrtf(bv[c + 1] + BN_EPS) * bg[c + 1] + bb[c + 1];
    x0 = x0 > 0.f ? x0 : expm1f(x0);
    x1 = x1 > 0.f ? x1 : expm1f(x1);

    *(float2*)&g_h2[(size_t)warp * HIDC + c] = make_float2(0.f, 0.f);
    if (lane == 0) g_sum2[warp] = 0.f;

    float z = x0 * Wc[c + 0] + x1 * Wc[c + 1];
    z += __shfl_xor_sync(0xffffffffu, z, 16);
    z += __shfl_xor_sync(0xffffffffu, z, 8);
    z += __shfl_xor_sync(0xffffffffu, z, 4);
    z += __shfl_xor_sync(0xffffffffu, z, 2);
    z += __shfl_xor_sync(0xffffffffu, z, 1);

    if (lane == 0) {
        z += bc[0];
        out[warp] = 1.f / (1.f + __expf(-z));
    }
}

// ---------------- launch -----------------------------------------------------
extern "C" void kernel_launch(void* const* d_in, const int* in_sizes, int n_in,
                              void* d_out, int out_size)
{
    const float* x    = (const float*)d_in[0];
    const int*   ei   = (const int*)  d_in[1];
    const float* W1l  = (const float*)d_in[2];
    const float* b1l  = (const float*)d_in[3];
    const float* W1r  = (const float*)d_in[4];
    const float* b1r  = (const float*)d_in[5];
    const float* att1 = (const float*)d_in[6];
    const float* bias1= (const float*)d_in[7];
    const float* bn1g = (const float*)d_in[8];
    const float* bn1b = (const float*)d_in[9];
    const float* bn1m = (const float*)d_in[10];
    const float* bn1v = (const float*)d_in[11];
    const float* W2l  = (const float*)d_in[12];
    const float* b2l  = (const float*)d_in[13];
    const float* W2r  = (const float*)d_in[14];
    const float* b2r  = (const float*)d_in[15];
    const float* att2 = (const float*)d_in[16];
    const float* bias2= (const float*)d_in[17];
    const float* bn2g = (const float*)d_in[18];
    const float* bn2b = (const float*)d_in[19];
    const float* bn2m = (const float*)d_in[20];
    const float* bn2v = (const float*)d_in[21];
    const float* Wc   = (const float*)d_in[22];
    const float* bc   = (const float*)d_in[23];
    float* out = (float*)d_out;

    const int edge1Blocks = ((ETOT / 2) * 16 + 255) / 256;  // 2 edges / 16 lanes
    const int edge2Blocks = ((ETOT / 2) * 8  + 255) / 256;  // 2 edges / 8 lanes
    const int rowBlocks   = (NN + 31) / 32;

    // layer 1
    k_gemm1<<<rowBlocks, C1>>>(x, W1l, b1l, W1r, b1r);
    k_edge1<<<edge1Blocks, 256>>>(ei, att1);
    k_epi1<<<(NN * C1 / 4 + 255) / 256, 256>>>(bias1, bn1g, bn1b, bn1m, bn1v);

    // layer 2
    k_gemm2<<<rowBlocks, HIDC>>>(W2l, b2l, W2r, b2r);
    k_edge2<<<edge2Blocks, 256>>>(ei, att2);

    // epilogue + classifier
    k_final<<<(NN * 32 + 255) / 256, 256>>>(bias2, bn2g, bn2b, bn2m, bn2v, Wc, bc, out);
}

// round 14
// speedup vs baseline: 1.9758x; 1.4991x over previous
#include <cuda_runtime.h>
#include <cuda_fp16.h>
#include <cstdint>

#define NN      50000
#define EE      800000
#define ETOT    (EE + NN)        // edges + self loops (850000, even)
#define IN_CH   256
#define HIDC    64
#define HEADS   2
#define C1      (HEADS * HIDC)   // 128
#define BN_EPS  1e-5f

// ---------------- scratch (static device arrays; no allocation) --------------
__device__ __half g_xl1h[NN * C1];   // fp16 edge operands
__device__ __half g_xr1h[NN * C1];
__device__ float  g_sum1[NN * HEADS];
__device__ float  g_h1 [NN * C1];    // layer-1: accumulates sum(p * xl), fp32
__device__ float  g_hm [NN * C1];    // after bn1 + elu
__device__ __half g_xl2h[NN * HIDC];
__device__ __half g_xr2h[NN * HIDC];
__device__ float  g_sum2[NN];
__device__ float  g_h2 [NN * HIDC];  // layer-2: accumulates sum(p * xl), fp32
__device__ __half g_w1t[2 * C1 * IN_CH];   // W1 cat, TRANSPOSED [2M][K] fp16
__device__ __half g_w2t[2 * HIDC * C1];    // W2 cat, TRANSPOSED [2M][K] fp16

// ---------------- helpers ----------------------------------------------------
__device__ __forceinline__ float lrelu(float v) { return v > 0.f ? v : 0.2f * v; }

__device__ __forceinline__ void red_add_v4(float* addr, float4 v) {
    asm volatile("red.global.add.v4.f32 [%0], {%1, %2, %3, %4};"
                 :: "l"(addr), "f"(v.x), "f"(v.y), "f"(v.z), "f"(v.w) : "memory");
}

__device__ __forceinline__ uint32_t smem_u32(const void* p) {
    return (uint32_t)__cvta_generic_to_shared(p);
}

#define LDSM_X4(r0, r1, r2, r3, addr) \
    asm volatile("ldmatrix.sync.aligned.m8n8.x4.shared.b16 {%0,%1,%2,%3}, [%4];" \
                 : "=r"(r0), "=r"(r1), "=r"(r2), "=r"(r3) : "r"(addr))

#define MMA16816(acc, a0, a1, a2, a3, b0, b1) \
    asm volatile("mma.sync.aligned.m16n8k16.row.col.f32.f16.f16.f32 " \
                 "{%0,%1,%2,%3}, {%4,%5,%6,%7}, {%8,%9}, {%0,%1,%2,%3};" \
                 : "+f"((acc)[0]), "+f"((acc)[1]), "+f"((acc)[2]), "+f"((acc)[3]) \
                 : "r"(a0), "r"(a1), "r"(a2), "r"(a3), "r"(b0), "r"(b1))

// logit contribution for 8 fp16 channel-pairs vs att coefficients
__device__ __forceinline__ float logit8(uint4 ar, uint4 br, float4 at0, float4 at1)
{
    const __half2* ah = (const __half2*)&ar;
    const __half2* bh = (const __half2*)&br;
    float2 a0 = __half22float2(ah[0]), a1 = __half22float2(ah[1]);
    float2 a2 = __half22float2(ah[2]), a3 = __half22float2(ah[3]);
    float2 b0 = __half22float2(bh[0]), b1 = __half22float2(bh[1]);
    float2 b2 = __half22float2(bh[2]), b3 = __half22float2(bh[3]);
    return at0.x * lrelu(a0.x + b0.x) + at0.y * lrelu(a0.y + b0.y)
         + at0.z * lrelu(a1.x + b1.x) + at0.w * lrelu(a1.y + b1.y)
         + at1.x * lrelu(a2.x + b2.x) + at1.y * lrelu(a2.y + b2.y)
         + at1.z * lrelu(a3.x + b3.x) + at1.w * lrelu(a3.y + b3.y);
}

__device__ __forceinline__ void scale8(uint4 ar, float p, float4& v0, float4& v1)
{
    const __half2* ah = (const __half2*)&ar;
    float2 a0 = __half22float2(ah[0]), a1 = __half22float2(ah[1]);
    float2 a2 = __half22float2(ah[2]), a3 = __half22float2(ah[3]);
    v0 = make_float4(a0.x * p, a0.y * p, a1.x * p, a1.y * p);
    v1 = make_float4(a2.x * p, a2.y * p, a3.x * p, a3.y * p);
}

// ---------------- weight convert: fp32 [K][M]x2 -> fp16 transposed [2M][K] ---
__global__ void k_wcvt1(const float* __restrict__ Wl, const float* __restrict__ Wr)
{
    constexpr int K = IN_CH, M = C1;
    int tid = blockIdx.x * blockDim.x + threadIdx.x;
    if (tid >= 2 * M * K) return;
    int c = tid / K, k = tid % K;
    float v = (c < M) ? Wl[k * M + c] : Wr[k * M + (c - M)];
    g_w1t[tid] = __float2half(v);
}
__global__ void k_wcvt2(const float* __restrict__ Wl, const float* __restrict__ Wr)
{
    constexpr int K = C1, M = HIDC;
    int tid = blockIdx.x * blockDim.x + threadIdx.x;
    if (tid >= 2 * M * K) return;
    int c = tid / K, k = tid % K;
    float v = (c < M) ? Wl[k * M + c] : Wr[k * M + (c - M)];
    g_w2t[tid] = __float2half(v);
}

// ---------------- tensor-core dual GEMM --------------------------------------
// LAYER 1: A = x (arg),   K=256, MHALF=128, out = g_x{l,r}1h
// LAYER 2: A = g_hm,      K=128, MHALF=64,  out = g_x{l,r}2h (+ zeros g_sum1)
// Block: 512 threads = 16 warps (8 row-groups x 2 col-warps), 128-row tile.
// Warp (wr, wc): rows wr*16..+15, all MHALF cols of matrix wc.
// A and Wt staged in smem padded to K+8 halves (conflict-free ldmatrix).
template<int LAYER>
__global__ __launch_bounds__(512) void k_mma_gemm(
    const float* __restrict__ Aparam,
    const float* __restrict__ bl, const float* __restrict__ br)
{
    constexpr int K     = (LAYER == 1) ? IN_CH : C1;
    constexpr int MHALF = (LAYER == 1) ? C1 : HIDC;
    constexpr int M2    = 2 * MHALF;
    constexpr int ROWS  = 128;
    constexpr int SK    = K + 8;          // padded stride (halves)
    constexpr int NT    = MHALF / 8;      // mma n-tiles per warp

    const float*  A    = (LAYER == 1) ? Aparam : (const float*)g_hm;
    const __half* Wt   = (LAYER == 1) ? g_w1t : g_w2t;
    __half*       outl = (LAYER == 1) ? g_xl1h : g_xl2h;
    __half*       outr = (LAYER == 1) ? g_xr1h : g_xr2h;

    extern __shared__ __half sh[];
    __half* As = sh;                      // [ROWS][SK]
    __half* Ws = sh + ROWS * SK;          // [M2][SK]

    const int tid = threadIdx.x;
    const int r0  = blockIdx.x * ROWS;

    // stage A (fp32 -> fp16), zero-pad OOB rows
    for (int i = tid * 4; i < ROWS * K; i += 512 * 4) {
        int row = i / K, kk = i % K;
        float4 v = (r0 + row < NN) ? *(const float4*)&A[(size_t)(r0 + row) * K + kk]
                                   : make_float4(0.f, 0.f, 0.f, 0.f);
        __half2* dst = (__half2*)&As[row * SK + kk];
        dst[0] = __floats2half2_rn(v.x, v.y);
        dst[1] = __floats2half2_rn(v.z, v.w);
    }
    // stage Wt (fp16, already transposed)
    for (int i = tid * 8; i < M2 * K; i += 512 * 8) {
        int row = i / K, kk = i % K;
        *(uint4*)&Ws[row * SK + kk] = *(const uint4*)&Wt[row * K + kk];
    }
    // layer 2: restore g_sum1 zero state (this kernel never reads it;
    // previous reader k_epi1 finished before this launch)
    if (LAYER == 2 && tid < 2 * ROWS) {
        int idx = blockIdx.x * (2 * ROWS) + tid;
        if (idx < 2 * NN) g_sum1[idx] = 0.f;
    }
    __syncthreads();

    const int warp = tid >> 5, lane = tid & 31;
    const int wr = warp >> 1, wc = warp & 1;
    const int lr = lane & 7,  g  = lane >> 3;

    // ldmatrix lane->address mappings
    const uint32_t aAddr0 = smem_u32(As) +
        (uint32_t)(((wr * 16 + lr + (g & 1) * 8) * SK + (g >> 1) * 8) * 2);
    const int rowB_off = lr + (g >> 1) * 8;
    const int colB     = (g & 1) * 8;
    const uint32_t wsBase = smem_u32(Ws);

    float acc[NT][4];
#pragma unroll
    for (int nt = 0; nt < NT; nt++)
#pragma unroll
        for (int j = 0; j < 4; j++) acc[nt][j] = 0.f;

    for (int kc = 0; kc < K / 16; kc++) {
        const int k0 = kc * 16;
        uint32_t a0, a1, a2, a3;
        LDSM_X4(a0, a1, a2, a3, aAddr0 + (uint32_t)(k0 * 2));
#pragma unroll
        for (int ntp = 0; ntp < NT / 2; ntp++) {
            int n0p = wc * MHALF + ntp * 16;
            uint32_t b0, b1, b2, b3;
            LDSM_X4(b0, b1, b2, b3,
                    wsBase + (uint32_t)(((n0p + rowB_off) * SK + k0 + colB) * 2));
            MMA16816(acc[2 * ntp],     a0, a1, a2, a3, b0, b1);
            MMA16816(acc[2 * ntp + 1], a0, a1, a2, a3, b2, b3);
        }
    }

    // epilogue: +bias, fp16 store
    const float* bs  = wc ? br : bl;
    __half*      out = wc ? outr : outl;
    const int row0 = r0 + wr * 16 + (lane >> 2);
    const int row1 = row0 + 8;
    const int cb   = (lane & 3) * 2;
#pragma unroll
    for (int nt = 0; nt < NT; nt++) {
        int lc = nt * 8 + cb;
        float b0v = bs[lc], b1v = bs[lc + 1];
        if (row0 < NN)
            *(__half2*)&out[(size_t)row0 * MHALF + lc] =
                __floats2half2_rn(acc[nt][0] + b0v, acc[nt][1] + b1v);
        if (row1 < NN)
            *(__half2*)&out[(size_t)row1 * MHALF + lc] =
                __floats2half2_rn(acc[nt][2] + b0v, acc[nt][3] + b1v);
    }
}

// ---------------- layer-1 FUSED edge pass: 2 edges per thread ----------------
__global__ void k_edge1(const int* __restrict__ ei, const float* __restrict__ att)
{
    int gid = blockIdx.x * blockDim.x + threadIdx.x;
    int gp  = gid >> 4;                    // 16 lanes per edge PAIR
    int l   = gid & 15;
    int e0  = gp * 2;
    if (e0 >= ETOT) return;

    int src0, dst0, src1, dst1;
    if (e0 < EE) {
        int2 sp = *(const int2*)&ei[e0];
        int2 dp = *(const int2*)&ei[EE + e0];
        src0 = sp.x; src1 = sp.y; dst0 = dp.x; dst1 = dp.y;
    } else {
        src0 = dst0 = e0 - EE;
        src1 = dst1 = e0 + 1 - EE;
    }

    int ch = l * 8;
    uint4 ar0 = *(const uint4*)&g_xl1h[(size_t)src0 * C1 + ch];
    uint4 br0 = *(const uint4*)&g_xr1h[(size_t)dst0 * C1 + ch];
    uint4 ar1 = *(const uint4*)&g_xl1h[(size_t)src1 * C1 + ch];
    uint4 br1 = *(const uint4*)&g_xr1h[(size_t)dst1 * C1 + ch];

    float4 at0 = *(const float4*)&att[ch];
    float4 at1 = *(const float4*)&att[ch + 4];

    float s0 = logit8(ar0, br0, at0, at1);
    float s1 = logit8(ar1, br1, at0, at1);

    s0 += __shfl_xor_sync(0xffffffffu, s0, 4);
    s1 += __shfl_xor_sync(0xffffffffu, s1, 4);
    s0 += __shfl_xor_sync(0xffffffffu, s0, 2);
    s1 += __shfl_xor_sync(0xffffffffu, s1, 2);
    s0 += __shfl_xor_sync(0xffffffffu, s0, 1);
    s1 += __shfl_xor_sync(0xffffffffu, s1, 1);

    float p0 = __expf(s0);
    float p1 = __expf(s1);

    if ((l & 7) == 0) {
        int h = l >> 3;
        atomicAdd(&g_sum1[(size_t)dst0 * 2 + h], p0);
        atomicAdd(&g_sum1[(size_t)dst1 * 2 + h], p1);
    }

    float4 v0, v1;
    scale8(ar0, p0, v0, v1);
    float* hb0 = &g_h1[(size_t)dst0 * C1 + ch];
    red_add_v4(hb0,     v0);
    red_add_v4(hb0 + 4, v1);

    scale8(ar1, p1, v0, v1);
    float* hb1 = &g_h1[(size_t)dst1 * C1 + ch];
    red_add_v4(hb1,     v0);
    red_add_v4(hb1 + 4, v1);
}

// ---------------- layer-1 epilogue: /sum, +bias, bn, elu (float4) ------------
__global__ void k_epi1(const float* __restrict__ bias,
                       const float* __restrict__ bg, const float* __restrict__ bb,
                       const float* __restrict__ bm, const float* __restrict__ bv)
{
    int i4 = (blockIdx.x * blockDim.x + threadIdx.x) * 4;
    if (i4 >= NN * C1) return;
    int c    = i4 & (C1 - 1);
    int node = i4 >> 7;
    int h    = c >> 6;
    float inv_s = __fdividef(1.f, g_sum1[node * 2 + h]);

    float4 hv = *(const float4*)&g_h1[i4];
    float4 bi = *(const float4*)&bias[c];
    float4 gm = *(const float4*)&bg[c];
    float4 bt = *(const float4*)&bb[c];
    float4 mu = *(const float4*)&bm[c];
    float4 vr = *(const float4*)&bv[c];

    float x0 = (hv.x * inv_s + bi.x - mu.x) * rsqrtf(vr.x + BN_EPS) * gm.x + bt.x;
    float x1 = (hv.y * inv_s + bi.y - mu.y) * rsqrtf(vr.y + BN_EPS) * gm.y + bt.y;
    float x2 = (hv.z * inv_s + bi.z - mu.z) * rsqrtf(vr.z + BN_EPS) * gm.z + bt.z;
    float x3 = (hv.w * inv_s + bi.w - mu.w) * rsqrtf(vr.w + BN_EPS) * gm.w + bt.w;

    float4 o;
    o.x = x0 > 0.f ? x0 : expm1f(x0);
    o.y = x1 > 0.f ? x1 : expm1f(x1);
    o.z = x2 > 0.f ? x2 : expm1f(x2);
    o.w = x3 > 0.f ? x3 : expm1f(x3);
    *(float4*)&g_hm[i4] = o;
    *(float4*)&g_h1[i4] = make_float4(0.f, 0.f, 0.f, 0.f);
}

// ---------------- layer-2 FUSED edge pass: 2 edges per thread ----------------
__global__ void k_edge2(const int* __restrict__ ei, const float* __restrict__ att)
{
    int gid = blockIdx.x * blockDim.x + threadIdx.x;
    int gp  = gid >> 3;                    // 8 lanes per edge PAIR
    int l   = gid & 7;
    int e0  = gp * 2;
    if (e0 >= ETOT) return;

    int src0, dst0, src1, dst1;
    if (e0 < EE) {
        int2 sp = *(const int2*)&ei[e0];
        int2 dp = *(const int2*)&ei[EE + e0];
        src0 = sp.x; src1 = sp.y; dst0 = dp.x; dst1 = dp.y;
    } else {
        src0 = dst0 = e0 - EE;
        src1 = dst1 = e0 + 1 - EE;
    }

    int ch = l * 8;
    uint4 ar0 = *(const uint4*)&g_xl2h[(size_t)src0 * HIDC + ch];
    uint4 br0 = *(const uint4*)&g_xr2h[(size_t)dst0 * HIDC + ch];
    uint4 ar1 = *(const uint4*)&g_xl2h[(size_t)src1 * HIDC + ch];
    uint4 br1 = *(const uint4*)&g_xr2h[(size_t)dst1 * HIDC + ch];

    float4 at0 = *(const float4*)&att[ch];
    float4 at1 = *(const float4*)&att[ch + 4];

    float s0 = logit8(ar0, br0, at0, at1);
    float s1 = logit8(ar1, br1, at0, at1);

    s0 += __shfl_xor_sync(0xffffffffu, s0, 4);
    s1 += __shfl_xor_sync(0xffffffffu, s1, 4);
    s0 += __shfl_xor_sync(0xffffffffu, s0, 2);
    s1 += __shfl_xor_sync(0xffffffffu, s1, 2);
    s0 += __shfl_xor_sync(0xffffffffu, s0, 1);
    s1 += __shfl_xor_sync(0xffffffffu, s1, 1);

    float p0 = __expf(s0);
    float p1 = __expf(s1);

    if (l == 0) {
        atomicAdd(&g_sum2[dst0], p0);
        atomicAdd(&g_sum2[dst1], p1);
    }

    float4 v0, v1;
    scale8(ar0, p0, v0, v1);
    float* hb0 = &g_h2[(size_t)dst0 * HIDC + ch];
    red_add_v4(hb0,     v0);
    red_add_v4(hb0 + 4, v1);

    scale8(ar1, p1, v0, v1);
    float* hb1 = &g_h2[(size_t)dst1 * HIDC + ch];
    red_add_v4(hb1,     v0);
    red_add_v4(hb1 + 4, v1);
}

// ---------------- final: /sum, +bias2, bn2, elu, classifier, sigmoid ---------
__global__ void k_final(const float* __restrict__ bias,
                        const float* __restrict__ bg, const float* __restrict__ bb,
                        const float* __restrict__ bm, const float* __restrict__ bv,
                        const float* __restrict__ Wc, const float* __restrict__ bc,
                        float* __restrict__ out)
{
    int warp = (blockIdx.x * blockDim.x + threadIdx.x) >> 5;
    int lane = threadIdx.x & 31;
    if (warp >= NN) return;

    float inv_s = __fdividef(1.f, g_sum2[warp]);
    int c = lane * 2;
    float2 h  = *(const float2*)&g_h2[(size_t)warp * HIDC + c];
    float x0 = h.x * inv_s + bias[c + 0];
    float x1 = h.y * inv_s + bias[c + 1];
    x0 = (x0 - bm[c + 0]) * rsqrtf(bv[c + 0] + BN_EPS) * bg[c + 0] + bb[c + 0];
    x1 = (x1 - bm[c + 1]) * rsqrtf(bv[c + 1] + BN_EPS) * bg[c + 1] + bb[c + 1];
    x0 = x0 > 0.f ? x0 : expm1f(x0);
    x1 = x1 > 0.f ? x1 : expm1f(x1);

    *(float2*)&g_h2[(size_t)warp * HIDC + c] = make_float2(0.f, 0.f);
    if (lane == 0) g_sum2[warp] = 0.f;

    float z = x0 * Wc[c + 0] + x1 * Wc[c + 1];
    z += __shfl_xor_sync(0xffffffffu, z, 16);
    z += __shfl_xor_sync(0xffffffffu, z, 8);
    z += __shfl_xor_sync(0xffffffffu, z, 4);
    z += __shfl_xor_sync(0xffffffffu, z, 2);
    z += __shfl_xor_sync(0xffffffffu, z, 1);

    if (lane == 0) {
        z += bc[0];
        out[warp] = 1.f / (1.f + __expf(-z));
    }
}

// ---------------- launch -----------------------------------------------------
extern "C" void kernel_launch(void* const* d_in, const int* in_sizes, int n_in,
                              void* d_out, int out_size)
{
    const float* x    = (const float*)d_in[0];
    const int*   ei   = (const int*)  d_in[1];
    const float* W1l  = (const float*)d_in[2];
    const float* b1l  = (const float*)d_in[3];
    const float* W1r  = (const float*)d_in[4];
    const float* b1r  = (const float*)d_in[5];
    const float* att1 = (const float*)d_in[6];
    const float* bias1= (const float*)d_in[7];
    const float* bn1g = (const float*)d_in[8];
    const float* bn1b = (const float*)d_in[9];
    const float* bn1m = (const float*)d_in[10];
    const float* bn1v = (const float*)d_in[11];
    const float* W2l  = (const float*)d_in[12];
    const float* b2l  = (const float*)d_in[13];
    const float* W2r  = (const float*)d_in[14];
    const float* b2r  = (const float*)d_in[15];
    const float* att2 = (const float*)d_in[16];
    const float* bias2= (const float*)d_in[17];
    const float* bn2g = (const float*)d_in[18];
    const float* bn2b = (const float*)d_in[19];
    const float* bn2m = (const float*)d_in[20];
    const float* bn2v = (const float*)d_in[21];
    const float* Wc   = (const float*)d_in[22];
    const float* bc   = (const float*)d_in[23];
    float* out = (float*)d_out;

    const int edge1Blocks = ((ETOT / 2) * 16 + 255) / 256;
    const int edge2Blocks = ((ETOT / 2) * 8  + 255) / 256;
    const int gemmBlocks  = (NN + 127) / 128;            // 391

    // dynamic smem: As[128][K+8] + Ws[2M][K+8] halves
    const int smem1 = (128 * (IN_CH + 8) + 2 * C1   * (IN_CH + 8)) * 2;  // 202752
    const int smem2 = (128 * (C1 + 8)    + 2 * HIDC * (C1 + 8))    * 2;  // 69632
    static bool attr_set = false;
    if (!attr_set) {
        cudaFuncSetAttribute(k_mma_gemm<1>, cudaFuncAttributeMaxDynamicSharedMemorySize, smem1);
        cudaFuncSetAttribute(k_mma_gemm<2>, cudaFuncAttributeMaxDynamicSharedMemorySize, smem2);
        attr_set = true;
    }

    // layer 1
    k_wcvt1<<<(2 * C1 * IN_CH + 255) / 256, 256>>>(W1l, W1r);
    k_mma_gemm<1><<<gemmBlocks, 512, smem1>>>(x, b1l, b1r);
    k_edge1<<<edge1Blocks, 256>>>(ei, att1);
    k_epi1<<<(NN * C1 / 4 + 255) / 256, 256>>>(bias1, bn1g, bn1b, bn1m, bn1v);

    // layer 2
    k_wcvt2<<<(2 * HIDC * C1 + 255) / 256, 256>>>(W2l, W2r);
    k_mma_gemm<2><<<gemmBlocks, 512, smem2>>>(x /*unused*/, b2l, b2r);
    k_edge2<<<edge2Blocks, 256>>>(ei, att2);

    // epilogue + classifier
    k_final<<<(NN * 32 + 255) / 256, 256>>>(bias2, bn2g, bn2b, bn2m, bn2v, Wc, bc, out);
}